// round 17
// baseline (speedup 1.0000x reference)
#include <cuda_runtime.h>
#include <cuda_bf16.h>

#define WG_EPS 1e-8f
#define BLK 256
#define CTAS (148 * 3)   // persistent: 3 CTAs/SM at ~85 regs

// Packed per-Gaussian input record in registers:
// [0:3) loc1, [3:6) loc2, [6:9) scale1, [9:12) scale2, [12:21) rot1, [21:30) rot2
__device__ __forceinline__ void load30(
    float* __restrict__ d, int b,
    const float* __restrict__ loc1, const float* __restrict__ scale1,
    const float* __restrict__ rot1,
    const float* __restrict__ loc2, const float* __restrict__ scale2,
    const float* __restrict__ rot2)
{
#pragma unroll
    for (int i = 0; i < 3; i++) {
        d[0 + i]  = __ldg(loc1   + 3 * b + i);
        d[3 + i]  = __ldg(loc2   + 3 * b + i);
        d[6 + i]  = __ldg(scale1 + 3 * b + i);
        d[9 + i]  = __ldg(scale2 + 3 * b + i);
    }
#pragma unroll
    for (int i = 0; i < 9; i++) {
        d[12 + i] = __ldg(rot1 + 9 * b + i);
        d[21 + i] = __ldg(rot2 + 9 * b + i);
    }
}

__device__ __forceinline__ float wg_compute(const float* __restrict__ g)
{
    const float* l1 = g + 0;
    const float* l2 = g + 3;
    float s1[3], s2[3];
#pragma unroll
    for (int i = 0; i < 3; i++) {
        s1[i] = fmaxf(g[6 + i], WG_EPS);
        s2[i] = fmaxf(g[9 + i], WG_EPS);
    }
    const float* r1 = g + 12;
    const float* r2 = g + 21;

    float d0 = l1[0] - l2[0], d1 = l1[1] - l2[1], d2 = l1[2] - l2[2];
    float loc_diff2 = d0 * d0 + d1 * d1 + d2 * d2;

    float cov2[3][3];
#pragma unroll
    for (int i = 0; i < 3; i++) {
#pragma unroll
        for (int k = i; k < 3; k++) {
            float v = r2[3 * i + 0] * s2[0] * r2[3 * k + 0]
                    + r2[3 * i + 1] * s2[1] * r2[3 * k + 1]
                    + r2[3 * i + 2] * s2[2] * r2[3 * k + 2];
            cov2[i][k] = v;
            cov2[k][i] = v;
        }
    }
    float tr_cov2 = cov2[0][0] + cov2[1][1] + cov2[2][2];

    float T[3][3];
#pragma unroll
    for (int j = 0; j < 3; j++)
#pragma unroll
        for (int l = 0; l < 3; l++)
            T[j][l] = cov2[j][0] * r1[0 * 3 + l]
                    + cov2[j][1] * r1[1 * 3 + l]
                    + cov2[j][2] * r1[2 * 3 + l];

    float M[3][3];
#pragma unroll
    for (int i = 0; i < 3; i++)
#pragma unroll
        for (int l = 0; l < 3; l++)
            M[i][l] = r1[0 * 3 + i] * T[0][l]
                    + r1[1 * 3 + i] * T[1][l]
                    + r1[2 * 3 + i] * T[2][l];

    float q0 = sqrtf(s1[0]), q1 = sqrtf(s1[1]), q2 = sqrtf(s1[2]);
    float a00 = s1[0] * M[0][0] + WG_EPS;
    float a11 = s1[1] * M[1][1] + WG_EPS;
    float a22 = s1[2] * M[2][2] + WG_EPS;
    float a01 = q0 * q1 * 0.5f * (M[0][1] + M[1][0]);
    float a02 = q0 * q2 * 0.5f * (M[0][2] + M[2][0]);
    float a12 = q1 * q2 * 0.5f * (M[1][2] + M[2][1]);

    // s = tr(E^{1/2}) via invariants + monotone Newton (R13 method)
    float I1 = a00 + a11 + a22;
    float I2 = (a00 * a11 - a01 * a01)
             + (a00 * a22 - a02 * a02)
             + (a11 * a22 - a12 * a12);
    float I3 = a00 * (a11 * a22 - a12 * a12)
             - a01 * (a01 * a22 - a12 * a02)
             + a02 * (a01 * a12 - a11 * a02);
    I1 = fmaxf(I1, 3.0f * WG_EPS);
    I2 = fmaxf(I2, 0.0f);
    I3 = fmaxf(I3, 0.0f);

    float c8 = 8.0f * sqrtf(I3);
    float K  = I1 * I1 - 4.0f * I2;
    float s  = sqrtf(I1 + 2.0f * sqrtf(3.0f * I2));

#pragma unroll
    for (int it = 0; it < 5; it++) {
        float s2v = s * s;
        float f   = (s2v - 2.0f * I1) * s2v - c8 * s + K;
        float fp  = s * (4.0f * s2v - 4.0f * I1) - c8;
        s -= f / fmaxf(fp, 1e-20f);
    }
    float sum_sqrt = fmaxf(s, 0.0f);

    float cov_w = (s1[0] + s1[1] + s1[2]) + tr_cov2 - 2.0f * sum_sqrt;
    cov_w = fmaxf(cov_w, 0.0f);
    return sqrtf(fmaxf(loc_diff2 + cov_w, WG_EPS));
}

__global__ __launch_bounds__(BLK, 3) void wasserstein_gaussian_kernel(
    const float* __restrict__ loc1,
    const float* __restrict__ scale1,
    const float* __restrict__ rot1,
    const float* __restrict__ loc2,
    const float* __restrict__ scale2,
    const float* __restrict__ rot2,
    float* __restrict__ out,
    int B)
{
    const int stride = gridDim.x * blockDim.x;
    int b = blockIdx.x * blockDim.x + threadIdx.x;
    if (b >= B) return;

    // Software pipeline: while computing Gaussian b, the loads for b+stride
    // are already in flight -> every warp keeps ~30 outstanding LDGs even
    // during its compute phase.
    float cur[30], nxt[30];
    load30(cur, b, loc1, scale1, rot1, loc2, scale2, rot2);

    for (;;) {
        int bn = b + stride;
        bool have_next = (bn < B);
        if (have_next)
            load30(nxt, bn, loc1, scale1, rot1, loc2, scale2, rot2);

        out[b] = wg_compute(cur);

        if (!have_next) break;
        b = bn;
#pragma unroll
        for (int i = 0; i < 30; i++) cur[i] = nxt[i];
    }
}

extern "C" void kernel_launch(void* const* d_in, const int* in_sizes, int n_in,
                              void* d_out, int out_size)
{
    const float* loc1   = (const float*)d_in[0];
    const float* scale1 = (const float*)d_in[1];
    const float* rot1   = (const float*)d_in[2];
    const float* loc2   = (const float*)d_in[3];
    const float* scale2 = (const float*)d_in[4];
    const float* rot2   = (const float*)d_in[5];
    float* out = (float*)d_out;

    int B = in_sizes[0] / 3;
    int blocks = CTAS;
    int maxb = (B + BLK - 1) / BLK;
    if (blocks > maxb) blocks = maxb;

    wasserstein_gaussian_kernel<<<blocks, BLK>>>(
        loc1, scale1, rot1, loc2, scale2, rot2, out, B);
}